// round 13
// baseline (speedup 1.0000x reference)
#include <cuda_runtime.h>
#include <cuda_bf16.h>
#include <math.h>

// Problem constants
#define NB 128      // batch
#define NP 196      // pixels
#define ND 512      // ENC = H = E = A = 512
#define NV 32000    // vocab
#define NL 20       // caption length
#define NT 19       // decode steps
#define NG 2048     // 4*H
#define NAG 1024    // att2+beta width
#define NHP 3072    // merged h-projection width [att2|gate|gates_h]

// ---------------------------------------------------------------------------
// Scratch (device globals; no allocations allowed)
// ---------------------------------------------------------------------------
__device__ __align__(16) float g_att1[(size_t)NB * NP * ND];
__device__ __align__(16) __nv_bfloat16 g_fhi[(size_t)NB * NP * ND];
__device__ __align__(16) __nv_bfloat16 g_flo[(size_t)NB * NP * ND];
__device__ __align__(16) __nv_bfloat16 g_wfch[(size_t)NV * ND];
__device__ __align__(16) __nv_bfloat16 g_wfcl[(size_t)NV * ND];
__device__ __align__(16) __nv_bfloat16 g_wagh[(size_t)NHP * ND];  // [w_dec|w_beta|w_hh]
__device__ __align__(16) __nv_bfloat16 g_wagl[(size_t)NHP * ND];
__device__ __align__(16) __nv_bfloat16 g_waweh[(size_t)NG * ND];  // w_ih[:,512:1024]
__device__ __align__(16) __nv_bfloat16 g_wawel[(size_t)NG * ND];
__device__ __align__(16) __nv_bfloat16 g_wembh[(size_t)NG * ND];  // w_ih[:,0:512]
__device__ __align__(16) __nv_bfloat16 g_wembl[(size_t)NG * ND];
__device__ __align__(16) __nv_bfloat16 g_wench[(size_t)ND * ND];
__device__ __align__(16) __nv_bfloat16 g_wencl[(size_t)ND * ND];
__device__ float g_bag[NAG];
__device__ float g_bcat[NG];
__device__ float g_fmean[NB * ND];
__device__ float g_h[NB * ND];
__device__ float g_c[NB * ND];
__device__ float g_hproj[2 * NB * NHP];                  // split-K=2 partials
__device__ float g_awep[2 * NB * NG];                    // split-K=2 partials
__device__ float g_embpre[(size_t)NT * NB * NG];         // emb-gates, all steps
__device__ __align__(16) __nv_bfloat16 g_embh[(size_t)NT * NB * ND];
__device__ __align__(16) __nv_bfloat16 g_embl[(size_t)NT * NB * ND];
__device__ __align__(16) __nv_bfloat16 g_awehi[NB * ND];
__device__ __align__(16) __nv_bfloat16 g_awelo[NB * ND];
__device__ __align__(16) __nv_bfloat16 g_hnallh[(size_t)NT * NB * ND]; // all h_new
__device__ __align__(16) __nv_bfloat16 g_hnalll[(size_t)NT * NB * ND];
__device__ __align__(16) __nv_bfloat16 g_hh[NB * ND];    // masked h
__device__ __align__(16) __nv_bfloat16 g_hl[NB * ND];

__device__ __forceinline__ float sigf(float x) { return 1.0f / (1.0f + expf(-x)); }

__device__ __forceinline__ void split2(float x, __nv_bfloat16* hi, __nv_bfloat16* lo)
{
    __nv_bfloat16 h = __float2bfloat16(x);
    *hi = h;
    *lo = __float2bfloat16(x - __bfloat162float(h));
}

// ---------------------------------------------------------------------------
// bf16x3 tensor-core GEMM with register-prefetch pipelining.
// C[m,n] = sum_k A[m,k]*W[n,k] (+ bias[n]); acc = Ah*Wh + Ah*Wl + Al*Wh.
// BM=128, BN=64, BK=32, 256 thr, 8 warps (4Mx2N), warp tile 32x32.
// M%128==0, N%64==0, K%32==0.  blockIdx.z = K-chunk (A/W advance z*K,
// C advances z*csplit).
// permute!=0 (batched FC): blockIdx.x = M-tile (= one t), blockIdx.y = N-tile
// (so same-weight blocks are scheduled adjacently); epilogue scatters row
// r -> (b*NT+t)*ldc with length masking; warps whose 32 rows are all masked
// (lengths sorted descending -> test lengths[mw]) skip all MMA work.
// ---------------------------------------------------------------------------
#define TBM 128
#define TBN 64
#define TBK 32
#define TLD 40   // BK + 8 pad (bf16); 80B row stride -> conflict-free frags

__device__ __forceinline__ void mma16816(float* c, const unsigned* a, const unsigned* b)
{
    asm volatile(
        "mma.sync.aligned.m16n8k16.row.col.f32.bf16.bf16.f32 "
        "{%0,%1,%2,%3}, {%4,%5,%6,%7}, {%8,%9}, {%0,%1,%2,%3};\n"
        : "+f"(c[0]), "+f"(c[1]), "+f"(c[2]), "+f"(c[3])
        : "r"(a[0]), "r"(a[1]), "r"(a[2]), "r"(a[3]), "r"(b[0]), "r"(b[1]));
}

__global__ __launch_bounds__(256) void gemm_bf16x3(
    const __nv_bfloat16* __restrict__ Ah, const __nv_bfloat16* __restrict__ Al,
    int lda,
    const __nv_bfloat16* __restrict__ Wh, const __nv_bfloat16* __restrict__ Wl,
    int ldw,
    const float* __restrict__ bias, float* __restrict__ C,
    int K, long ldc, long coff, long csplit,
    const int* __restrict__ lengths, int permute, int tbase)
{
    __shared__ __nv_bfloat16 sAh[TBM * TLD];
    __shared__ __nv_bfloat16 sAl[TBM * TLD];
    __shared__ __nv_bfloat16 sWh[TBN * TLD];
    __shared__ __nv_bfloat16 sWl[TBN * TLD];

    const int tid  = threadIdx.x;
    const int wid  = tid >> 5;
    const int lane = tid & 31;
    const int g    = lane >> 2;
    const int tq   = lane & 3;
    const int mw   = (wid & 3) * 32;
    const int nw   = (wid >> 2) * 32;
    const int bmIdx = permute ? blockIdx.x : blockIdx.y;
    const int bnIdx = permute ? blockIdx.y : blockIdx.x;
    const long bm  = (long)bmIdx * TBM;
    const long bn  = (long)bnIdx * TBN;
    const long koff = (long)blockIdx.z * K;
    coff += (long)blockIdx.z * csplit;

    // Warp-level activity (permute/FC path only): this warp's rows are
    // b = mw..mw+31 of step t = tbase + bmIdx. lengths sorted descending,
    // so all rows inactive iff smallest b (mw) is inactive.
    int wact = 1;
    if (permute) {
        int tIdx = tbase + bmIdx;
        wact = (tIdx < lengths[mw] - 1) ? 1 : 0;
    }

    // per-thread load coords
    const int arow0 = tid >> 2,  ac8 = (tid & 3) * 8;      // + _mi*64 rows
    const int wrow  = tid >> 2,  wc8 = (tid & 3) * 8;

    float acc[2][4][4];
#pragma unroll
    for (int mi = 0; mi < 2; mi++)
#pragma unroll
        for (int ni = 0; ni < 4; ni++)
#pragma unroll
            for (int q = 0; q < 4; q++) acc[mi][ni][q] = 0.f;

    uint4 ra_h[2], ra_l[2], rw_h, rw_l;

    // NOTE: k0 is evaluated ONCE into _kk before the inner loop — the inner
    // loop variable must NOT shadow any identifier used in the k0 expression.
#define LDG_TILE(k0)                                                          \
    do {                                                                      \
        const long _kk = (long)(k0);                                          \
        _Pragma("unroll")                                                     \
        for (int _mi = 0; _mi < 2; _mi++) {                                   \
            long go = (bm + arow0 + _mi * 64) * (long)lda + koff + _kk + ac8; \
            ra_h[_mi] = *(const uint4*)&Ah[go];                               \
            ra_l[_mi] = *(const uint4*)&Al[go];                               \
        }                                                                     \
        long gw = (bn + wrow) * (long)ldw + koff + _kk + wc8;                 \
        rw_h = *(const uint4*)&Wh[gw];                                        \
        rw_l = *(const uint4*)&Wl[gw];                                        \
    } while (0)

#define STS_TILE()                                                            \
    do {                                                                      \
        _Pragma("unroll")                                                     \
        for (int _mi = 0; _mi < 2; _mi++) {                                   \
            *(uint4*)&sAh[(arow0 + _mi * 64) * TLD + ac8] = ra_h[_mi];        \
            *(uint4*)&sAl[(arow0 + _mi * 64) * TLD + ac8] = ra_l[_mi];        \
        }                                                                     \
        *(uint4*)&sWh[wrow * TLD + wc8] = rw_h;                               \
        *(uint4*)&sWl[wrow * TLD + wc8] = rw_l;                               \
    } while (0)

    const int nIter = K / TBK;
    LDG_TILE(0);

    for (int i = 0; i < nIter; i++) {
        STS_TILE();
        __syncthreads();
        if (i + 1 < nIter) LDG_TILE((i + 1) * TBK);   // overlap with compute

        if (wact) {
#pragma unroll
            for (int ks = 0; ks < TBK; ks += 16) {
                unsigned ah[2][4], al[2][4], bh[4][2], bl[4][2];
                const int kc = ks + tq * 2;
#pragma unroll
                for (int mi = 0; mi < 2; mi++) {
                    int r0 = mw + mi * 16 + g;
                    ah[mi][0] = *(const unsigned*)&sAh[r0 * TLD + kc];
                    ah[mi][1] = *(const unsigned*)&sAh[(r0 + 8) * TLD + kc];
                    ah[mi][2] = *(const unsigned*)&sAh[r0 * TLD + kc + 8];
                    ah[mi][3] = *(const unsigned*)&sAh[(r0 + 8) * TLD + kc + 8];
                    al[mi][0] = *(const unsigned*)&sAl[r0 * TLD + kc];
                    al[mi][1] = *(const unsigned*)&sAl[(r0 + 8) * TLD + kc];
                    al[mi][2] = *(const unsigned*)&sAl[r0 * TLD + kc + 8];
                    al[mi][3] = *(const unsigned*)&sAl[(r0 + 8) * TLD + kc + 8];
                }
#pragma unroll
                for (int ni = 0; ni < 4; ni++) {
                    int wr = nw + ni * 8 + g;
                    bh[ni][0] = *(const unsigned*)&sWh[wr * TLD + kc];
                    bh[ni][1] = *(const unsigned*)&sWh[wr * TLD + kc + 8];
                    bl[ni][0] = *(const unsigned*)&sWl[wr * TLD + kc];
                    bl[ni][1] = *(const unsigned*)&sWl[wr * TLD + kc + 8];
                }
#pragma unroll
                for (int mi = 0; mi < 2; mi++)
#pragma unroll
                    for (int ni = 0; ni < 4; ni++) {
                        mma16816(acc[mi][ni], ah[mi], bh[ni]);
                        mma16816(acc[mi][ni], ah[mi], bl[ni]);
                        mma16816(acc[mi][ni], al[mi], bh[ni]);
                    }
            }
        }
        __syncthreads();
    }

    // ---- epilogue ----
#pragma unroll
    for (int mi = 0; mi < 2; mi++) {
        int r0 = mw + mi * 16 + g;
        long rowA = bm + r0, rowB = rowA + 8;
        long oA, oB;
        int actA = 1, actB = 1;
        if (permute) {
            int tA = tbase + (int)(rowA >> 7), bA = (int)(rowA & 127);
            int tB = tbase + (int)(rowB >> 7), bB = (int)(rowB & 127);
            oA = ((long)bA * NT + tA) * ldc;
            oB = ((long)bB * NT + tB) * ldc;
            actA = (tA < lengths[bA] - 1) ? 1 : 0;
            actB = (tB < lengths[bB] - 1) ? 1 : 0;
        } else {
            oA = coff + rowA * ldc;
            oB = coff + rowB * ldc;
        }
#pragma unroll
        for (int ni = 0; ni < 4; ni++) {
            long col = bn + nw + ni * 8 + tq * 2;
            float b0 = bias ? bias[col] : 0.f;
            float b1 = bias ? bias[col + 1] : 0.f;
            float v0 = acc[mi][ni][0] + b0, v1 = acc[mi][ni][1] + b1;
            float v2 = acc[mi][ni][2] + b0, v3 = acc[mi][ni][3] + b1;
            if (!actA) { v0 = 0.f; v1 = 0.f; }
            if (!actB) { v2 = 0.f; v3 = 0.f; }
            *(float2*)&C[oA + col] = make_float2(v0, v1);
            *(float2*)&C[oB + col] = make_float2(v2, v3);
        }
    }
#undef LDG_TILE
#undef STS_TILE
}

// ---------------------------------------------------------------------------
// fp32 tiled SGEMM (init h0/c0 only)
// ---------------------------------------------------------------------------
#define BM 64
#define BN 64
#define BK 16

__global__ __launch_bounds__(256) void sgemm_nt(
    const float* __restrict__ A, const float* __restrict__ W,
    const float* __restrict__ bias, float* __restrict__ C,
    int M, int N, int K)
{
    __shared__ float As[BK][BM];
    __shared__ float Ws[BK][BN];

    const int bm = blockIdx.y * BM;
    const int bn = blockIdx.x * BN;
    const int tid = threadIdx.x;
    const int tr  = tid >> 4;
    const int tc  = tid & 15;
    const int lr  = tid >> 2;
    const int lk  = (tid & 3) * 4;

    float acc[4][4];
#pragma unroll
    for (int i = 0; i < 4; i++)
#pragma unroll
        for (int j = 0; j < 4; j++) acc[i][j] = 0.f;

    for (int k0 = 0; k0 < K; k0 += BK) {
        float4 av = *(const float4*)(&A[(long)(bm + lr) * K + k0 + lk]);
        As[lk + 0][lr] = av.x; As[lk + 1][lr] = av.y;
        As[lk + 2][lr] = av.z; As[lk + 3][lr] = av.w;
        float4 wv = *(const float4*)(&W[(long)(bn + lr) * K + k0 + lk]);
        Ws[lk + 0][lr] = wv.x; Ws[lk + 1][lr] = wv.y;
        Ws[lk + 2][lr] = wv.z; Ws[lk + 3][lr] = wv.w;
        __syncthreads();
#pragma unroll
        for (int kk = 0; kk < BK; kk++) {
            float4 a4 = *(const float4*)(&As[kk][tr * 4]);
            float4 w4 = *(const float4*)(&Ws[kk][tc * 4]);
            float a[4] = {a4.x, a4.y, a4.z, a4.w};
            float w[4] = {w4.x, w4.y, w4.z, w4.w};
#pragma unroll
            for (int i = 0; i < 4; i++)
#pragma unroll
                for (int j = 0; j < 4; j++) acc[i][j] = fmaf(a[i], w[j], acc[i][j]);
        }
        __syncthreads();
    }
#pragma unroll
    for (int i = 0; i < 4; i++) {
        int row = bm + tr * 4 + i;
#pragma unroll
        for (int j = 0; j < 4; j++) {
            int col = bn + tc * 4 + j;
            C[(long)row * N + col] = acc[i][j] + bias[col];
        }
    }
}

// ---------------------------------------------------------------------------
// Small kernels
// ---------------------------------------------------------------------------
__global__ void k_fmean(const float* __restrict__ features)
{
    int b = blockIdx.x, e = threadIdx.x;
    const float* f = features + (long)b * NP * ND + e;
    float s = 0.f;
#pragma unroll 4
    for (int p = 0; p < NP; p++) s += f[(long)p * ND];
    g_fmean[b * ND + e] = s * (1.0f / (float)NP);
}

__global__ void k_split(const float* __restrict__ src,
                        __nv_bfloat16* __restrict__ hi,
                        __nv_bfloat16* __restrict__ lo, long n)
{
    long i = (long)blockIdx.x * blockDim.x + threadIdx.x;
    if (i >= n) return;
    split2(src[i], &hi[i], &lo[i]);
}

// One-shot setup: all weight splits/packs in a single launch.
#define SN_F   ((long)NB * NP * ND)   // features split
#define SN_W   ((long)NV * ND)        // w_fc split
#define SN_E   ((long)ND * ND)        // w_enc split
#define SN_AG  ((long)NHP * ND)       // [w_dec|w_beta|w_hh] pack
#define SN_AWE ((long)NG * ND)        // w_ih[:,512:1024]
#define SN_EMB ((long)NG * ND)        // w_ih[:,0:512]
#define SN_TOT (SN_F + SN_W + SN_E + SN_AG + SN_AWE + SN_EMB)

__global__ void k_setup(const float* __restrict__ features,
                        const float* __restrict__ w_fc,
                        const float* __restrict__ w_enc,
                        const float* __restrict__ w_ih, const float* __restrict__ w_hh,
                        const float* __restrict__ b_ih, const float* __restrict__ b_hh,
                        const float* __restrict__ w_dec, const float* __restrict__ b_dec,
                        const float* __restrict__ w_beta, const float* __restrict__ b_beta)
{
    long idx = (long)blockIdx.x * blockDim.x + threadIdx.x;
    if (idx < NG)  g_bcat[idx] = b_ih[idx] + b_hh[idx];
    if (idx < NAG) g_bag[idx] = (idx < 512) ? b_dec[idx] : b_beta[idx - 512];
    if (idx >= SN_TOT) return;
    if (idx < SN_F) { split2(features[idx], &g_fhi[idx], &g_flo[idx]); return; }
    idx -= SN_F;
    if (idx < SN_W) { split2(w_fc[idx], &g_wfch[idx], &g_wfcl[idx]); return; }
    idx -= SN_W;
    if (idx < SN_E) { split2(w_enc[idx], &g_wench[idx], &g_wencl[idx]); return; }
    idx -= SN_E;
    if (idx < SN_AG) {
        int j = (int)(idx / ND), k = (int)(idx % ND);
        float v;
        if (j < 512)       v = w_dec[(long)j * ND + k];
        else if (j < 1024) v = w_beta[(long)(j - 512) * ND + k];
        else               v = w_hh[(long)(j - 1024) * ND + k];
        split2(v, &g_wagh[idx], &g_wagl[idx]);
        return;
    }
    idx -= SN_AG;
    if (idx < SN_AWE) {
        int j = (int)(idx / ND), k = (int)(idx % ND);
        split2(w_ih[(long)j * 1024 + 512 + k], &g_waweh[idx], &g_wawel[idx]);
        return;
    }
    idx -= SN_AWE;
    {
        int j = (int)(idx / ND), k = (int)(idx % ND);
        split2(w_ih[(long)j * 1024 + k], &g_wembh[idx], &g_wembl[idx]);
    }
}

// Gather + split embeddings for all steps: row r = t*NB+b -> embed_w[captions[b,t]]
__global__ void k_embgather(const float* __restrict__ embed_w,
                            const int* __restrict__ captions)
{
    long idx = (long)blockIdx.x * blockDim.x + threadIdx.x;
    if (idx >= (long)NT * NB * ND) return;
    int e = (int)(idx % ND);
    int r = (int)(idx / ND);
    int t = r / NB, b = r % NB;
    int tok = captions[b * NL + t];
    split2(embed_w[(long)tok * ND + e], &g_embh[idx], &g_embl[idx]);
}

// Fused attention: escore + softmax + context. One block per b, 512 thr.
// att2/gatepre from 2 hproj split-K partials + bias. Writes awe hi/lo.
// Context sum reads bf16-hi features (halved traffic; error damped through
// gates; alphas unaffected since e-scores use fp32 att1).
__global__ __launch_bounds__(512) void k_att(
    const int* __restrict__ lengths,
    const float* __restrict__ w_full,
    float* __restrict__ out, long alpha_off, int t)
{
    const int b = blockIdx.x;
    const int tid = threadIdx.x;
    const int w = tid >> 5, lane = tid & 31;
    __shared__ float satt2[ND];
    __shared__ float swf[ND];
    __shared__ float sal[NP];
    __shared__ float red[512];

    satt2[tid] = g_hproj[(long)b * NHP + tid]
               + g_hproj[(long)NB * NHP + (long)b * NHP + tid] + g_bag[tid];
    swf[tid] = w_full[tid];
    __syncthreads();

    // ---- e scores: warp per p-row ----
    for (int p = w; p < NP; p += 16) {
        const float4* a1 = (const float4*)(g_att1 + ((long)b * NP + p) * ND);
        float s = 0.f;
#pragma unroll
        for (int j = 0; j < 4; j++) {
            int idx = lane + j * 32;
            float4 x = a1[idx];
            int k = idx * 4;
            s = fmaf(fmaxf(x.x + satt2[k + 0], 0.f), swf[k + 0], s);
            s = fmaf(fmaxf(x.y + satt2[k + 1], 0.f), swf[k + 1], s);
            s = fmaf(fmaxf(x.z + satt2[k + 2], 0.f), swf[k + 2], s);
            s = fmaf(fmaxf(x.w + satt2[k + 3], 0.f), swf[k + 3], s);
        }
#pragma unroll
        for (int o = 16; o > 0; o >>= 1) s += __shfl_xor_sync(0xffffffffu, s, o);
        if (lane == 0) sal[p] = s;
    }
    __syncthreads();

    // ---- softmax over NP ----
    float v = (tid < NP) ? sal[tid] : -1e30f;
    red[tid] = v; __syncthreads();
#pragma unroll
    for (int s = 256; s > 0; s >>= 1) { if (tid < s) red[tid] = fmaxf(red[tid], red[tid + s]); __syncthreads(); }
    float mx = red[0]; __syncthreads();
    float ex = (tid < NP) ? expf(v - mx) : 0.f;
    red[tid] = ex; __syncthreads();
#pragma unroll
    for (int s = 256; s > 0; s >>= 1) { if (tid < s) red[tid] += red[tid + s]; __syncthreads(); }
    float inv = 1.0f / red[0];
    int act = (t < lengths[b] - 1) ? 1 : 0;
    if (tid < NP) {
        float a = ex * inv;
        sal[tid] = a;
        out[alpha_off + ((long)b * NT + t) * NP + tid] = act ? a : 0.f;
    }
    __syncthreads();

    // ---- context: awe = sigmoid(gatepre) * (alpha @ features_bf16hi) ----
    const int e = tid;
    const __nv_bfloat16* f = g_fhi + (long)b * NP * ND + e;
    float s = 0.f;
#pragma unroll 4
    for (int p = 0; p < NP; p++)
        s = fmaf(sal[p], __bfloat162float(f[(long)p * ND]), s);
    float gpre = g_hproj[(long)b * NHP + 512 + e]
               + g_hproj[(long)NB * NHP + (long)b * NHP + 512 + e] + g_bag[512 + e];
    float awe = s * sigf(gpre);
    split2(awe, &g_awehi[b * ND + e], &g_awelo[b * ND + e]);
}

// LSTM pointwise: gates = embpre[t] + hproj(2 partials, cols 1024+) +
// awep(2 partials) + bcat; updates h/c, archives h_new split.
__global__ void k_lstm(const int* __restrict__ lengths, int t)
{
    int b = blockIdx.x, j = threadIdx.x;   // 512 threads
    const float* ep = g_embpre + ((long)t * NB + b) * NG;
    const float* h0p = g_hproj + (long)b * NHP + 1024;
    const float* h1p = g_hproj + (long)NB * NHP + (long)b * NHP + 1024;
    const float* a0p = g_awep + (long)b * NG;
    const float* a1p = g_awep + (long)NB * NG + (long)b * NG;
#define GSUM(o) (ep[o] + h0p[o] + h1p[o] + a0p[o] + a1p[o] + g_bcat[o])
    float pi = GSUM(j);
    float pf = GSUM(512 + j);
    float pg = GSUM(1024 + j);
    float po = GSUM(1536 + j);
#undef GSUM
    float ig = sigf(pi), fg = sigf(pf), gg = tanhf(pg), og = sigf(po);
    float cold = g_c[b * ND + j], hold = g_h[b * ND + j];
    float cn = fg * cold + ig * gg;
    float hn = og * tanhf(cn);
    long ai = ((long)t * NB + b) * ND + j;
    split2(hn, &g_hnallh[ai], &g_hnalll[ai]);
    int act = (t < lengths[b] - 1) ? 1 : 0;
    float h2 = act ? hn : hold;
    g_h[b * ND + j] = h2;
    g_c[b * ND + j] = act ? cn : cold;
    split2(h2, &g_hh[b * ND + j], &g_hl[b * ND + j]);
}

// ---------------------------------------------------------------------------
// Launch
// ---------------------------------------------------------------------------
extern "C" void kernel_launch(void* const* d_in, const int* in_sizes, int n_in,
                              void* d_out, int out_size)
{
    const float* features = (const float*)d_in[0];
    const int*   captions = (const int*)  d_in[1];
    const int*   lengths  = (const int*)  d_in[2];
    const float* w_enc_att= (const float*)d_in[3];
    const float* b_enc_att= (const float*)d_in[4];
    const float* w_dec_att= (const float*)d_in[5];
    const float* b_dec_att= (const float*)d_in[6];
    const float* w_full   = (const float*)d_in[7];
    // d_in[8] = b_full : softmax-invariant constant, unused
    const float* embed_w  = (const float*)d_in[9];
    const float* w_ih     = (const float*)d_in[10];
    const float* b_ih     = (const float*)d_in[11];
    const float* w_hh     = (const float*)d_in[12];
    const float* b_hh     = (const float*)d_in[13];
    const float* w_init_h = (const float*)d_in[14];
    const float* b_init_h = (const float*)d_in[15];
    const float* w_init_c = (const float*)d_in[16];
    const float* b_init_c = (const float*)d_in[17];
    const float* w_beta   = (const float*)d_in[18];
    const float* b_beta   = (const float*)d_in[19];
    const float* w_fc     = (const float*)d_in[20];
    const float* b_fc     = (const float*)d_in[21];
    float* out = (float*)d_out;

    float *p_att1, *p_fmean, *p_h, *p_c, *p_hproj, *p_awep, *p_embpre;
    __nv_bfloat16 *p_fhi, *p_flo, *p_wfch, *p_wfcl, *p_wagh, *p_wagl,
                  *p_waweh, *p_wawel, *p_wembh, *p_wembl, *p_wench, *p_wencl,
                  *p_embh, *p_embl, *p_awehi, *p_awelo,
                  *p_hh, *p_hl, *p_hnallh, *p_hnalll;
    cudaGetSymbolAddress((void**)&p_att1,   g_att1);
    cudaGetSymbolAddress((void**)&p_fmean,  g_fmean);
    cudaGetSymbolAddress((void**)&p_h,      g_h);
    cudaGetSymbolAddress((void**)&p_c,      g_c);
    cudaGetSymbolAddress((void**)&p_hproj,  g_hproj);
    cudaGetSymbolAddress((void**)&p_awep,   g_awep);
    cudaGetSymbolAddress((void**)&p_embpre, g_embpre);
    cudaGetSymbolAddress((void**)&p_fhi,    g_fhi);
    cudaGetSymbolAddress((void**)&p_flo,    g_flo);
    cudaGetSymbolAddress((void**)&p_wfch,   g_wfch);
    cudaGetSymbolAddress((void**)&p_wfcl,   g_wfcl);
    cudaGetSymbolAddress((void**)&p_wagh,   g_wagh);
    cudaGetSymbolAddress((void**)&p_wagl,   g_wagl);
    cudaGetSymbolAddress((void**)&p_waweh,  g_waweh);
    cudaGetSymbolAddress((void**)&p_wawel,  g_wawel);
    cudaGetSymbolAddress((void**)&p_wembh,  g_wembh);
    cudaGetSymbolAddress((void**)&p_wembl,  g_wembl);
    cudaGetSymbolAddress((void**)&p_wench,  g_wench);
    cudaGetSymbolAddress((void**)&p_wencl,  g_wencl);
    cudaGetSymbolAddress((void**)&p_embh,   g_embh);
    cudaGetSymbolAddress((void**)&p_embl,   g_embl);
    cudaGetSymbolAddress((void**)&p_awehi,  g_awehi);
    cudaGetSymbolAddress((void**)&p_awelo,  g_awelo);
    cudaGetSymbolAddress((void**)&p_hh,     g_hh);
    cudaGetSymbolAddress((void**)&p_hl,     g_hl);
    cudaGetSymbolAddress((void**)&p_hnallh, g_hnallh);
    cudaGetSymbolAddress((void**)&p_hnalll, g_hnalll);

    // Side stream (lowest priority so chain dispatch wins) + events
    int prLow = 0, prHigh = 0;
    cudaDeviceGetStreamPriorityRange(&prLow, &prHigh);
    cudaStream_t side;
    cudaStreamCreateWithPriority(&side, cudaStreamNonBlocking, prLow);
    cudaEvent_t ev_setup, ev_embpre, ev_chunk[4], evf;
    cudaEventCreateWithFlags(&ev_setup,  cudaEventDisableTiming);
    cudaEventCreateWithFlags(&ev_embpre, cudaEventDisableTiming);
    for (int i = 0; i < 4; i++)
        cudaEventCreateWithFlags(&ev_chunk[i], cudaEventDisableTiming);
    cudaEventCreateWithFlags(&evf, cudaEventDisableTiming);

    const long PRED_SIZE = (long)NB * NT * NV;
    const long ALPHA_OFF = PRED_SIZE;

    // ---- Main-stream setup ----
    k_fmean<<<NB, ND>>>(features);
    {
        dim3 gi(ND / BN, NB / BM);
        sgemm_nt<<<gi, 256>>>(p_fmean, w_init_h, b_init_h, p_h, NB, ND, ND);
        sgemm_nt<<<gi, 256>>>(p_fmean, w_init_c, b_init_c, p_c, NB, ND, ND);
    }
    k_split<<<(NB * ND + 255) / 256, 256>>>(p_h, p_hh, p_hl, NB * ND);
    k_setup<<<(int)((SN_TOT + 255) / 256), 256>>>(features, w_fc, w_enc_att,
                                                  w_ih, w_hh, b_ih, b_hh,
                                                  w_dec_att, b_dec_att, w_beta, b_beta);
    cudaEventRecord(ev_setup, 0);

    // ---- Side-stream: emb gather + emb-gates for all steps ----
    cudaStreamWaitEvent(side, ev_setup, 0);
    {
        long n = (long)NT * NB * ND;
        k_embgather<<<(int)((n + 255) / 256), 256, 0, side>>>(embed_w, captions);
        dim3 grid(NG / TBN, (NT * NB) / TBM, 1);   // (32, 19)
        gemm_bf16x3<<<grid, 256, 0, side>>>(p_embh, p_embl, ND,
                                            p_wembh, p_wembl, ND,
                                            nullptr, p_embpre, ND, NG, 0, 0,
                                            nullptr, 0, 0);
        cudaEventRecord(ev_embpre, side);
    }

    // ---- Main: att1 = features @ w_enc^T + b  (25088 x 512, K=512) ----
    {
        dim3 grid(ND / TBN, (NB * NP) / TBM, 1);   // (8, 196)
        gemm_bf16x3<<<grid, 256>>>(p_fhi, p_flo, ND, p_wench, p_wencl, ND,
                                   b_enc_att, p_att1, ND, ND, 0, 0,
                                   nullptr, 0, 0);
    }
    cudaStreamWaitEvent(0, ev_embpre, 0);   // embpre ready before first lstm

    // ---- Decode loop ----
    const int chunk_t0[4] = {0, 6, 12, 18};
    const int chunk_nt[4] = {6, 6, 6, 1};
    int ci = 0;
    for (int t = 0; t < NT; t++) {
        // hproj = h @ [w_dec|w_beta|w_hh]^T, split-K=2  (128 x 3072)
        {
            dim3 grid(NHP / TBN, 1, 2);            // (48,1,2)
            gemm_bf16x3<<<grid, 256>>>(p_hh, p_hl, ND, p_wagh, p_wagl, ND,
                                       nullptr, p_hproj, 256, NHP, 0,
                                       (long)NB * NHP, nullptr, 0, 0);
        }
        // fused escore + softmax + context (emits awe split)
        k_att<<<NB, 512>>>(lengths, w_full, out, ALPHA_OFF, t);
        // awe-gates partials: awe @ w_awe^T, split-K=2  (128 x 2048)
        {
            dim3 grid(NG / TBN, 1, 2);             // (32,1,2)
            gemm_bf16x3<<<grid, 256>>>(p_awehi, p_awelo, ND, p_waweh, p_wawel, ND,
                                       nullptr, p_awep, 256, NG, 0,
                                       (long)NB * NG, nullptr, 0, 0);
        }
        k_lstm<<<NB, ND>>>(lengths, t);

        // chunk boundary -> batched FC for steps [t0, t0+nt) on side stream.
        // permute mode: grid.x = t-tiles (M), grid.y = N-tiles (weight reuse).
        if (ci < 4 && t == chunk_t0[ci] + chunk_nt[ci] - 1) {
            cudaEventRecord(ev_chunk[ci], 0);
            cudaStreamWaitEvent(side, ev_chunk[ci], 0);
            int t0 = chunk_t0[ci], nt = chunk_nt[ci];
            dim3 grid(nt, NV / TBN, 1);            // (nt, 500)
            gemm_bf16x3<<<grid, 256, 0, side>>>(
                p_hnallh + (long)t0 * NB * ND, p_hnalll + (long)t0 * NB * ND, ND,
                p_wfch, p_wfcl, ND,
                b_fc, out, ND, NV, 0, 0,
                lengths, 1, t0);
            ci++;
        }
    }
    cudaEventRecord(evf, side);
    cudaStreamWaitEvent(0, evf, 0);
}

// round 14
// speedup vs baseline: 1.0122x; 1.0122x over previous
#include <cuda_runtime.h>
#include <cuda_bf16.h>
#include <math.h>

// Problem constants
#define NB 128      // batch
#define NP 196      // pixels
#define ND 512      // ENC = H = E = A = 512
#define NV 32000    // vocab
#define NL 20       // caption length
#define NT 19       // decode steps
#define NG 2048     // 4*H
#define NAG 1024    // att2+beta width
#define NHP 3072    // merged h-projection width [att2|gate|gates_h]

// ---------------------------------------------------------------------------
// Scratch (device globals; no allocations allowed)
// ---------------------------------------------------------------------------
__device__ __align__(16) float g_att1[(size_t)NB * NP * ND];
__device__ __align__(16) __nv_bfloat16 g_fhi[(size_t)NB * NP * ND];
__device__ __align__(16) __nv_bfloat16 g_flo[(size_t)NB * NP * ND];
__device__ __align__(16) __nv_bfloat16 g_wfch[(size_t)NV * ND];
__device__ __align__(16) __nv_bfloat16 g_wfcl[(size_t)NV * ND];
__device__ __align__(16) __nv_bfloat16 g_wagh[(size_t)NHP * ND];  // [w_dec|w_beta|w_hh]
__device__ __align__(16) __nv_bfloat16 g_wagl[(size_t)NHP * ND];
__device__ __align__(16) __nv_bfloat16 g_waweh[(size_t)NG * ND];  // w_ih[:,512:1024]
__device__ __align__(16) __nv_bfloat16 g_wawel[(size_t)NG * ND];
__device__ __align__(16) __nv_bfloat16 g_wembh[(size_t)NG * ND];  // w_ih[:,0:512]
__device__ __align__(16) __nv_bfloat16 g_wembl[(size_t)NG * ND];
__device__ __align__(16) __nv_bfloat16 g_wench[(size_t)ND * ND];
__device__ __align__(16) __nv_bfloat16 g_wencl[(size_t)ND * ND];
__device__ float g_bag[NAG];
__device__ float g_bcat[NG];
__device__ float g_fmean[NB * ND];
__device__ float g_h[NB * ND];
__device__ float g_c[NB * ND];
__device__ float g_hproj[2 * NB * NHP];                  // split-K=2 partials
__device__ float g_awep[2 * NB * NG];                    // split-K=2 partials
__device__ float g_embpre[(size_t)NT * NB * NG];         // emb-gates, all steps
__device__ __align__(16) __nv_bfloat16 g_embh[(size_t)NT * NB * ND];
__device__ __align__(16) __nv_bfloat16 g_embl[(size_t)NT * NB * ND];
__device__ __align__(16) __nv_bfloat16 g_awehi[NB * ND];
__device__ __align__(16) __nv_bfloat16 g_awelo[NB * ND];
__device__ __align__(16) __nv_bfloat16 g_hnallh[(size_t)NT * NB * ND]; // all h_new
__device__ __align__(16) __nv_bfloat16 g_hnalll[(size_t)NT * NB * ND];
__device__ __align__(16) __nv_bfloat16 g_hh[NB * ND];    // masked h
__device__ __align__(16) __nv_bfloat16 g_hl[NB * ND];

__device__ __forceinline__ float sigf(float x) { return 1.0f / (1.0f + expf(-x)); }

__device__ __forceinline__ void split2(float x, __nv_bfloat16* hi, __nv_bfloat16* lo)
{
    __nv_bfloat16 h = __float2bfloat16(x);
    *hi = h;
    *lo = __float2bfloat16(x - __bfloat162float(h));
}

// ---------------------------------------------------------------------------
// bf16x3 tensor-core GEMM: register-prefetch pipelining + ldmatrix fragments.
// C[m,n] = sum_k A[m,k]*W[n,k] (+ bias[n]); acc = Ah*Wh + Ah*Wl + Al*Wh.
// BM=128, BN=64, BK=32, 256 thr, 8 warps (4Mx2N), warp tile 32x32.
// M%128==0, N%64==0, K%32==0.  blockIdx.z = K-chunk (A/W advance z*K,
// C advances z*csplit).
// permute!=0 (batched FC): blockIdx.x = M-tile (= one t), blockIdx.y = N-tile
// (same-weight blocks scheduled adjacently); epilogue scatters row
// r -> (b*NT+t)*ldc with length masking; warps whose 32 rows are all masked
// (lengths sorted descending -> test lengths[mw]) skip all fragment/MMA work.
// TLD=40 (80B row stride): ldmatrix row addrs hit distinct 16B banks
// (offsets/16 mod 8 = {0,5,2,7,4,1,6,3}) -> conflict-free.
// ---------------------------------------------------------------------------
#define TBM 128
#define TBN 64
#define TBK 32
#define TLD 40   // BK + 8 pad (bf16)

__device__ __forceinline__ void mma16816(float* c, const unsigned* a, const unsigned* b)
{
    asm volatile(
        "mma.sync.aligned.m16n8k16.row.col.f32.bf16.bf16.f32 "
        "{%0,%1,%2,%3}, {%4,%5,%6,%7}, {%8,%9}, {%0,%1,%2,%3};\n"
        : "+f"(c[0]), "+f"(c[1]), "+f"(c[2]), "+f"(c[3])
        : "r"(a[0]), "r"(a[1]), "r"(a[2]), "r"(a[3]), "r"(b[0]), "r"(b[1]));
}

__device__ __forceinline__ void ldsm4(unsigned& r0, unsigned& r1, unsigned& r2,
                                      unsigned& r3, unsigned addr)
{
    asm volatile("ldmatrix.sync.aligned.m8n8.x4.shared.b16 {%0,%1,%2,%3}, [%4];"
                 : "=r"(r0), "=r"(r1), "=r"(r2), "=r"(r3) : "r"(addr));
}

__global__ __launch_bounds__(256) void gemm_bf16x3(
    const __nv_bfloat16* __restrict__ Ah, const __nv_bfloat16* __restrict__ Al,
    int lda,
    const __nv_bfloat16* __restrict__ Wh, const __nv_bfloat16* __restrict__ Wl,
    int ldw,
    const float* __restrict__ bias, float* __restrict__ C,
    int K, long ldc, long coff, long csplit,
    const int* __restrict__ lengths, int permute, int tbase)
{
    __shared__ __nv_bfloat16 sAh[TBM * TLD];
    __shared__ __nv_bfloat16 sAl[TBM * TLD];
    __shared__ __nv_bfloat16 sWh[TBN * TLD];
    __shared__ __nv_bfloat16 sWl[TBN * TLD];

    const int tid  = threadIdx.x;
    const int wid  = tid >> 5;
    const int lane = tid & 31;
    const int g    = lane >> 2;
    const int tq   = lane & 3;
    const int mw   = (wid & 3) * 32;
    const int nw   = (wid >> 2) * 32;
    const int bmIdx = permute ? blockIdx.x : blockIdx.y;
    const int bnIdx = permute ? blockIdx.y : blockIdx.x;
    const long bm  = (long)bmIdx * TBM;
    const long bn  = (long)bnIdx * TBN;
    const long koff = (long)blockIdx.z * K;
    coff += (long)blockIdx.z * csplit;

    // Warp-level activity (FC path): lengths sorted descending, so this
    // warp's 32 rows are all inactive iff row mw is inactive.
    int wact = 1;
    if (permute) {
        int tIdx = tbase + bmIdx;
        wact = (tIdx < lengths[mw] - 1) ? 1 : 0;
    }

    // per-thread load coords
    const int arow0 = tid >> 2,  ac8 = (tid & 3) * 8;      // + _mi*64 rows
    const int wrow  = tid >> 2,  wc8 = (tid & 3) * 8;

    // ldmatrix per-thread address components (byte offsets into tile)
    const unsigned uAh = (unsigned)__cvta_generic_to_shared(sAh);
    const unsigned uAl = (unsigned)__cvta_generic_to_shared(sAl);
    const unsigned uWh = (unsigned)__cvta_generic_to_shared(sWh);
    const unsigned uWl = (unsigned)__cvta_generic_to_shared(sWl);
    const int aoff = ((mw + (lane & 15)) * TLD + ((lane >> 4) << 3)) * 2;
    const int boff = ((nw + ((lane >> 4) << 3) + (lane & 7)) * TLD +
                      (((lane >> 3) & 1) << 3)) * 2;

    float acc[2][4][4];
#pragma unroll
    for (int mi = 0; mi < 2; mi++)
#pragma unroll
        for (int ni = 0; ni < 4; ni++)
#pragma unroll
            for (int q = 0; q < 4; q++) acc[mi][ni][q] = 0.f;

    uint4 ra_h[2], ra_l[2], rw_h, rw_l;

    // NOTE: k0 evaluated ONCE into _kk before the inner loop (macro hygiene).
#define LDG_TILE(k0)                                                          \
    do {                                                                      \
        const long _kk = (long)(k0);                                          \
        _Pragma("unroll")                                                     \
        for (int _mi = 0; _mi < 2; _mi++) {                                   \
            long go = (bm + arow0 + _mi * 64) * (long)lda + koff + _kk + ac8; \
            ra_h[_mi] = *(const uint4*)&Ah[go];                               \
            ra_l[_mi] = *(const uint4*)&Al[go];                               \
        }                                                                     \
        long gw = (bn + wrow) * (long)ldw + koff + _kk + wc8;                 \
        rw_h = *(const uint4*)&Wh[gw];                                        \
        rw_l = *(const uint4*)&Wl[gw];                                        \
    } while (0)

#define STS_TILE()                                                            \
    do {                                                                      \
        _Pragma("unroll")                                                     \
        for (int _mi = 0; _mi < 2; _mi++) {                                   \
            *(uint4*)&sAh[(arow0 + _mi * 64) * TLD + ac8] = ra_h[_mi];        \
            *(uint4*)&sAl[(arow0 + _mi * 64) * TLD + ac8] = ra_l[_mi];        \
        }                                                                     \
        *(uint4*)&sWh[wrow * TLD + wc8] = rw_h;                               \
        *(uint4*)&sWl[wrow * TLD + wc8] = rw_l;                               \
    } while (0)

    const int nIter = K / TBK;
    LDG_TILE(0);

    for (int i = 0; i < nIter; i++) {
        STS_TILE();
        __syncthreads();
        if (i + 1 < nIter) LDG_TILE((i + 1) * TBK);   // overlap with compute

        if (wact) {
#pragma unroll
            for (int ks = 0; ks < TBK; ks += 16) {
                unsigned ah[2][4], al[2][4], bh[4][2], bl[4][2];
                const int kb = ks * 2;   // byte offset of k-column
#pragma unroll
                for (int mi = 0; mi < 2; mi++) {
                    unsigned ad = aoff + mi * (16 * TLD * 2) + kb;
                    ldsm4(ah[mi][0], ah[mi][1], ah[mi][2], ah[mi][3], uAh + ad);
                    ldsm4(al[mi][0], al[mi][1], al[mi][2], al[mi][3], uAl + ad);
                }
#pragma unroll
                for (int p = 0; p < 2; p++) {
                    unsigned bd = boff + p * (16 * TLD * 2) + kb;
                    ldsm4(bh[2*p][0], bh[2*p][1], bh[2*p+1][0], bh[2*p+1][1], uWh + bd);
                    ldsm4(bl[2*p][0], bl[2*p][1], bl[2*p+1][0], bl[2*p+1][1], uWl + bd);
                }
#pragma unroll
                for (int mi = 0; mi < 2; mi++)
#pragma unroll
                    for (int ni = 0; ni < 4; ni++) {
                        mma16816(acc[mi][ni], ah[mi], bh[ni]);
                        mma16816(acc[mi][ni], ah[mi], bl[ni]);
                        mma16816(acc[mi][ni], al[mi], bh[ni]);
                    }
            }
        }
        __syncthreads();
    }

    // ---- epilogue ----
#pragma unroll
    for (int mi = 0; mi < 2; mi++) {
        int r0 = mw + mi * 16 + g;
        long rowA = bm + r0, rowB = rowA + 8;
        long oA, oB;
        int actA = 1, actB = 1;
        if (permute) {
            int tA = tbase + (int)(rowA >> 7), bA = (int)(rowA & 127);
            int tB = tbase + (int)(rowB >> 7), bB = (int)(rowB & 127);
            oA = ((long)bA * NT + tA) * ldc;
            oB = ((long)bB * NT + tB) * ldc;
            actA = (tA < lengths[bA] - 1) ? 1 : 0;
            actB = (tB < lengths[bB] - 1) ? 1 : 0;
        } else {
            oA = coff + rowA * ldc;
            oB = coff + rowB * ldc;
        }
#pragma unroll
        for (int ni = 0; ni < 4; ni++) {
            long col = bn + nw + ni * 8 + tq * 2;
            float b0 = bias ? bias[col] : 0.f;
            float b1 = bias ? bias[col + 1] : 0.f;
            float v0 = acc[mi][ni][0] + b0, v1 = acc[mi][ni][1] + b1;
            float v2 = acc[mi][ni][2] + b0, v3 = acc[mi][ni][3] + b1;
            if (!actA) { v0 = 0.f; v1 = 0.f; }
            if (!actB) { v2 = 0.f; v3 = 0.f; }
            *(float2*)&C[oA + col] = make_float2(v0, v1);
            *(float2*)&C[oB + col] = make_float2(v2, v3);
        }
    }
#undef LDG_TILE
#undef STS_TILE
}

// ---------------------------------------------------------------------------
// fp32 tiled SGEMM (init h0/c0 only)
// ---------------------------------------------------------------------------
#define BM 64
#define BN 64
#define BK 16

__global__ __launch_bounds__(256) void sgemm_nt(
    const float* __restrict__ A, const float* __restrict__ W,
    const float* __restrict__ bias, float* __restrict__ C,
    int M, int N, int K)
{
    __shared__ float As[BK][BM];
    __shared__ float Ws[BK][BN];

    const int bm = blockIdx.y * BM;
    const int bn = blockIdx.x * BN;
    const int tid = threadIdx.x;
    const int tr  = tid >> 4;
    const int tc  = tid & 15;
    const int lr  = tid >> 2;
    const int lk  = (tid & 3) * 4;

    float acc[4][4];
#pragma unroll
    for (int i = 0; i < 4; i++)
#pragma unroll
        for (int j = 0; j < 4; j++) acc[i][j] = 0.f;

    for (int k0 = 0; k0 < K; k0 += BK) {
        float4 av = *(const float4*)(&A[(long)(bm + lr) * K + k0 + lk]);
        As[lk + 0][lr] = av.x; As[lk + 1][lr] = av.y;
        As[lk + 2][lr] = av.z; As[lk + 3][lr] = av.w;
        float4 wv = *(const float4*)(&W[(long)(bn + lr) * K + k0 + lk]);
        Ws[lk + 0][lr] = wv.x; Ws[lk + 1][lr] = wv.y;
        Ws[lk + 2][lr] = wv.z; Ws[lk + 3][lr] = wv.w;
        __syncthreads();
#pragma unroll
        for (int kk = 0; kk < BK; kk++) {
            float4 a4 = *(const float4*)(&As[kk][tr * 4]);
            float4 w4 = *(const float4*)(&Ws[kk][tc * 4]);
            float a[4] = {a4.x, a4.y, a4.z, a4.w};
            float w[4] = {w4.x, w4.y, w4.z, w4.w};
#pragma unroll
            for (int i = 0; i < 4; i++)
#pragma unroll
                for (int j = 0; j < 4; j++) acc[i][j] = fmaf(a[i], w[j], acc[i][j]);
        }
        __syncthreads();
    }
#pragma unroll
    for (int i = 0; i < 4; i++) {
        int row = bm + tr * 4 + i;
#pragma unroll
        for (int j = 0; j < 4; j++) {
            int col = bn + tc * 4 + j;
            C[(long)row * N + col] = acc[i][j] + bias[col];
        }
    }
}

// ---------------------------------------------------------------------------
// Small kernels
// ---------------------------------------------------------------------------
__global__ void k_fmean(const float* __restrict__ features)
{
    int b = blockIdx.x, e = threadIdx.x;
    const float* f = features + (long)b * NP * ND + e;
    float s = 0.f;
#pragma unroll 4
    for (int p = 0; p < NP; p++) s += f[(long)p * ND];
    g_fmean[b * ND + e] = s * (1.0f / (float)NP);
}

__global__ void k_split(const float* __restrict__ src,
                        __nv_bfloat16* __restrict__ hi,
                        __nv_bfloat16* __restrict__ lo, long n)
{
    long i = (long)blockIdx.x * blockDim.x + threadIdx.x;
    if (i >= n) return;
    split2(src[i], &hi[i], &lo[i]);
}

// One-shot setup: all weight splits/packs in a single launch.
#define SN_F   ((long)NB * NP * ND)   // features split
#define SN_W   ((long)NV * ND)        // w_fc split
#define SN_E   ((long)ND * ND)        // w_enc split
#define SN_AG  ((long)NHP * ND)       // [w_dec|w_beta|w_hh] pack
#define SN_AWE ((long)NG * ND)        // w_ih[:,512:1024]
#define SN_EMB ((long)NG * ND)        // w_ih[:,0:512]
#define SN_TOT (SN_F + SN_W + SN_E + SN_AG + SN_AWE + SN_EMB)

__global__ void k_setup(const float* __restrict__ features,
                        const float* __restrict__ w_fc,
                        const float* __restrict__ w_enc,
                        const float* __restrict__ w_ih, const float* __restrict__ w_hh,
                        const float* __restrict__ b_ih, const float* __restrict__ b_hh,
                        const float* __restrict__ w_dec, const float* __restrict__ b_dec,
                        const float* __restrict__ w_beta, const float* __restrict__ b_beta)
{
    long idx = (long)blockIdx.x * blockDim.x + threadIdx.x;
    if (idx < NG)  g_bcat[idx] = b_ih[idx] + b_hh[idx];
    if (idx < NAG) g_bag[idx] = (idx < 512) ? b_dec[idx] : b_beta[idx - 512];
    if (idx >= SN_TOT) return;
    if (idx < SN_F) { split2(features[idx], &g_fhi[idx], &g_flo[idx]); return; }
    idx -= SN_F;
    if (idx < SN_W) { split2(w_fc[idx], &g_wfch[idx], &g_wfcl[idx]); return; }
    idx -= SN_W;
    if (idx < SN_E) { split2(w_enc[idx], &g_wench[idx], &g_wencl[idx]); return; }
    idx -= SN_E;
    if (idx < SN_AG) {
        int j = (int)(idx / ND), k = (int)(idx % ND);
        float v;
        if (j < 512)       v = w_dec[(long)j * ND + k];
        else if (j < 1024) v = w_beta[(long)(j - 512) * ND + k];
        else               v = w_hh[(long)(j - 1024) * ND + k];
        split2(v, &g_wagh[idx], &g_wagl[idx]);
        return;
    }
    idx -= SN_AG;
    if (idx < SN_AWE) {
        int j = (int)(idx / ND), k = (int)(idx % ND);
        split2(w_ih[(long)j * 1024 + 512 + k], &g_waweh[idx], &g_wawel[idx]);
        return;
    }
    idx -= SN_AWE;
    {
        int j = (int)(idx / ND), k = (int)(idx % ND);
        split2(w_ih[(long)j * 1024 + k], &g_wembh[idx], &g_wembl[idx]);
    }
}

// Gather + split embeddings for all steps: row r = t*NB+b -> embed_w[captions[b,t]]
__global__ void k_embgather(const float* __restrict__ embed_w,
                            const int* __restrict__ captions)
{
    long idx = (long)blockIdx.x * blockDim.x + threadIdx.x;
    if (idx >= (long)NT * NB * ND) return;
    int e = (int)(idx % ND);
    int r = (int)(idx / ND);
    int t = r / NB, b = r % NB;
    int tok = captions[b * NL + t];
    split2(embed_w[(long)tok * ND + e], &g_embh[idx], &g_embl[idx]);
}

// Fused attention: escore + softmax + context. One block per b, 512 thr.
// att2/gatepre from 2 hproj split-K partials + bias. Writes awe hi/lo.
// Context sum uses fp32 features (full accuracy; preds error stays ~2e-6).
__global__ __launch_bounds__(512) void k_att(
    const int* __restrict__ lengths,
    const float* __restrict__ features,
    const float* __restrict__ w_full,
    float* __restrict__ out, long alpha_off, int t)
{
    const int b = blockIdx.x;
    const int tid = threadIdx.x;
    const int w = tid >> 5, lane = tid & 31;
    __shared__ float satt2[ND];
    __shared__ float swf[ND];
    __shared__ float sal[NP];
    __shared__ float red[512];

    satt2[tid] = g_hproj[(long)b * NHP + tid]
               + g_hproj[(long)NB * NHP + (long)b * NHP + tid] + g_bag[tid];
    swf[tid] = w_full[tid];
    __syncthreads();

    // ---- e scores: warp per p-row ----
    for (int p = w; p < NP; p += 16) {
        const float4* a1 = (const float4*)(g_att1 + ((long)b * NP + p) * ND);
        float s = 0.f;
#pragma unroll
        for (int j = 0; j < 4; j++) {
            int idx = lane + j * 32;
            float4 x = a1[idx];
            int k = idx * 4;
            s = fmaf(fmaxf(x.x + satt2[k + 0], 0.f), swf[k + 0], s);
            s = fmaf(fmaxf(x.y + satt2[k + 1], 0.f), swf[k + 1], s);
            s = fmaf(fmaxf(x.z + satt2[k + 2], 0.f), swf[k + 2], s);
            s = fmaf(fmaxf(x.w + satt2[k + 3], 0.f), swf[k + 3], s);
        }
#pragma unroll
        for (int o = 16; o > 0; o >>= 1) s += __shfl_xor_sync(0xffffffffu, s, o);
        if (lane == 0) sal[p] = s;
    }
    __syncthreads();

    // ---- softmax over NP ----
    float v = (tid < NP) ? sal[tid] : -1e30f;
    red[tid] = v; __syncthreads();
#pragma unroll
    for (int s = 256; s > 0; s >>= 1) { if (tid < s) red[tid] = fmaxf(red[tid], red[tid + s]); __syncthreads(); }
    float mx = red[0]; __syncthreads();
    float ex = (tid < NP) ? expf(v - mx) : 0.f;
    red[tid] = ex; __syncthreads();
#pragma unroll
    for (int s = 256; s > 0; s >>= 1) { if (tid < s) red[tid] += red[tid + s]; __syncthreads(); }
    float inv = 1.0f / red[0];
    int act = (t < lengths[b] - 1) ? 1 : 0;
    if (tid < NP) {
        float a = ex * inv;
        sal[tid] = a;
        out[alpha_off + ((long)b * NT + t) * NP + tid] = act ? a : 0.f;
    }
    __syncthreads();

    // ---- context: awe = sigmoid(gatepre) * (alpha @ features) ----
    const int e = tid;
    const float* f = features + (long)b * NP * ND + e;
    float s = 0.f;
#pragma unroll 4
    for (int p = 0; p < NP; p++) s = fmaf(sal[p], f[(long)p * ND], s);
    float gpre = g_hproj[(long)b * NHP + 512 + e]
               + g_hproj[(long)NB * NHP + (long)b * NHP + 512 + e] + g_bag[512 + e];
    float awe = s * sigf(gpre);
    split2(awe, &g_awehi[b * ND + e], &g_awelo[b * ND + e]);
}

// LSTM pointwise: gates = embpre[t] + hproj(2 partials, cols 1024+) +
// awep(2 partials) + bcat; updates h/c, archives h_new split.
__global__ void k_lstm(const int* __restrict__ lengths, int t)
{
    int b = blockIdx.x, j = threadIdx.x;   // 512 threads
    const float* ep = g_embpre + ((long)t * NB + b) * NG;
    const float* h0p = g_hproj + (long)b * NHP + 1024;
    const float* h1p = g_hproj + (long)NB * NHP + (long)b * NHP + 1024;
    const float* a0p = g_awep + (long)b * NG;
    const float* a1p = g_awep + (long)NB * NG + (long)b * NG;
#define GSUM(o) (ep[o] + h0p[o] + h1p[o] + a0p[o] + a1p[o] + g_bcat[o])
    float pi = GSUM(j);
    float pf = GSUM(512 + j);
    float pg = GSUM(1024 + j);
    float po = GSUM(1536 + j);
#undef GSUM
    float ig = sigf(pi), fg = sigf(pf), gg = tanhf(pg), og = sigf(po);
    float cold = g_c[b * ND + j], hold = g_h[b * ND + j];
    float cn = fg * cold + ig * gg;
    float hn = og * tanhf(cn);
    long ai = ((long)t * NB + b) * ND + j;
    split2(hn, &g_hnallh[ai], &g_hnalll[ai]);
    int act = (t < lengths[b] - 1) ? 1 : 0;
    float h2 = act ? hn : hold;
    g_h[b * ND + j] = h2;
    g_c[b * ND + j] = act ? cn : cold;
    split2(h2, &g_hh[b * ND + j], &g_hl[b * ND + j]);
}

// ---------------------------------------------------------------------------
// Launch
// ---------------------------------------------------------------------------
extern "C" void kernel_launch(void* const* d_in, const int* in_sizes, int n_in,
                              void* d_out, int out_size)
{
    const float* features = (const float*)d_in[0];
    const int*   captions = (const int*)  d_in[1];
    const int*   lengths  = (const int*)  d_in[2];
    const float* w_enc_att= (const float*)d_in[3];
    const float* b_enc_att= (const float*)d_in[4];
    const float* w_dec_att= (const float*)d_in[5];
    const float* b_dec_att= (const float*)d_in[6];
    const float* w_full   = (const float*)d_in[7];
    // d_in[8] = b_full : softmax-invariant constant, unused
    const float* embed_w  = (const float*)d_in[9];
    const float* w_ih     = (const float*)d_in[10];
    const float* b_ih     = (const float*)d_in[11];
    const float* w_hh     = (const float*)d_in[12];
    const float* b_hh     = (const float*)d_in[13];
    const float* w_init_h = (const float*)d_in[14];
    const float* b_init_h = (const float*)d_in[15];
    const float* w_init_c = (const float*)d_in[16];
    const float* b_init_c = (const float*)d_in[17];
    const float* w_beta   = (const float*)d_in[18];
    const float* b_beta   = (const float*)d_in[19];
    const float* w_fc     = (const float*)d_in[20];
    const float* b_fc     = (const float*)d_in[21];
    float* out = (float*)d_out;

    float *p_att1, *p_fmean, *p_h, *p_c, *p_hproj, *p_awep, *p_embpre;
    __nv_bfloat16 *p_fhi, *p_flo, *p_wfch, *p_wfcl, *p_wagh, *p_wagl,
                  *p_waweh, *p_wawel, *p_wembh, *p_wembl, *p_wench, *p_wencl,
                  *p_embh, *p_embl, *p_awehi, *p_awelo,
                  *p_hh, *p_hl, *p_hnallh, *p_hnalll;
    cudaGetSymbolAddress((void**)&p_att1,   g_att1);
    cudaGetSymbolAddress((void**)&p_fmean,  g_fmean);
    cudaGetSymbolAddress((void**)&p_h,      g_h);
    cudaGetSymbolAddress((void**)&p_c,      g_c);
    cudaGetSymbolAddress((void**)&p_hproj,  g_hproj);
    cudaGetSymbolAddress((void**)&p_awep,   g_awep);
    cudaGetSymbolAddress((void**)&p_embpre, g_embpre);
    cudaGetSymbolAddress((void**)&p_fhi,    g_fhi);
    cudaGetSymbolAddress((void**)&p_flo,    g_flo);
    cudaGetSymbolAddress((void**)&p_wfch,   g_wfch);
    cudaGetSymbolAddress((void**)&p_wfcl,   g_wfcl);
    cudaGetSymbolAddress((void**)&p_wagh,   g_wagh);
    cudaGetSymbolAddress((void**)&p_wagl,   g_wagl);
    cudaGetSymbolAddress((void**)&p_waweh,  g_waweh);
    cudaGetSymbolAddress((void**)&p_wawel,  g_wawel);
    cudaGetSymbolAddress((void**)&p_wembh,  g_wembh);
    cudaGetSymbolAddress((void**)&p_wembl,  g_wembl);
    cudaGetSymbolAddress((void**)&p_wench,  g_wench);
    cudaGetSymbolAddress((void**)&p_wencl,  g_wencl);
    cudaGetSymbolAddress((void**)&p_embh,   g_embh);
    cudaGetSymbolAddress((void**)&p_embl,   g_embl);
    cudaGetSymbolAddress((void**)&p_awehi,  g_awehi);
    cudaGetSymbolAddress((void**)&p_awelo,  g_awelo);
    cudaGetSymbolAddress((void**)&p_hh,     g_hh);
    cudaGetSymbolAddress((void**)&p_hl,     g_hl);
    cudaGetSymbolAddress((void**)&p_hnallh, g_hnallh);
    cudaGetSymbolAddress((void**)&p_hnalll, g_hnalll);

    // Side stream (lowest priority so chain dispatch wins) + events
    int prLow = 0, prHigh = 0;
    cudaDeviceGetStreamPriorityRange(&prLow, &prHigh);
    cudaStream_t side;
    cudaStreamCreateWithPriority(&side, cudaStreamNonBlocking, prLow);
    cudaEvent_t ev_setup, ev_embpre, ev_chunk[4], evf;
    cudaEventCreateWithFlags(&ev_setup,  cudaEventDisableTiming);
    cudaEventCreateWithFlags(&ev_embpre, cudaEventDisableTiming);
    for (int i = 0; i < 4; i++)
        cudaEventCreateWithFlags(&ev_chunk[i], cudaEventDisableTiming);
    cudaEventCreateWithFlags(&evf, cudaEventDisableTiming);

    const long PRED_SIZE = (long)NB * NT * NV;
    const long ALPHA_OFF = PRED_SIZE;

    // ---- Main-stream setup ----
    k_fmean<<<NB, ND>>>(features);
    {
        dim3 gi(ND / BN, NB / BM);
        sgemm_nt<<<gi, 256>>>(p_fmean, w_init_h, b_init_h, p_h, NB, ND, ND);
        sgemm_nt<<<gi, 256>>>(p_fmean, w_init_c, b_init_c, p_c, NB, ND, ND);
    }
    k_split<<<(NB * ND + 255) / 256, 256>>>(p_h, p_hh, p_hl, NB * ND);
    k_setup<<<(int)((SN_TOT + 255) / 256), 256>>>(features, w_fc, w_enc_att,
                                                  w_ih, w_hh, b_ih, b_hh,
                                                  w_dec_att, b_dec_att, w_beta, b_beta);
    cudaEventRecord(ev_setup, 0);

    // ---- Side-stream: emb gather + emb-gates for all steps ----
    cudaStreamWaitEvent(side, ev_setup, 0);
    {
        long n = (long)NT * NB * ND;
        k_embgather<<<(int)((n + 255) / 256), 256, 0, side>>>(embed_w, captions);
        dim3 grid(NG / TBN, (NT * NB) / TBM, 1);   // (32, 19)
        gemm_bf16x3<<<grid, 256, 0, side>>>(p_embh, p_embl, ND,
                                            p_wembh, p_wembl, ND,
                                            nullptr, p_embpre, ND, NG, 0, 0,
                                            nullptr, 0, 0);
        cudaEventRecord(ev_embpre, side);
    }

    // ---- Main: att1 = features @ w_enc^T + b  (25088 x 512, K=512) ----
    {
        dim3 grid(ND / TBN, (NB * NP) / TBM, 1);   // (8, 196)
        gemm_bf16x3<<<grid, 256>>>(p_fhi, p_flo, ND, p_wench, p_wencl, ND,
                                   b_enc_att, p_att1, ND, ND, 0, 0,
                                   nullptr, 0, 0);
    }
    cudaStreamWaitEvent(0, ev_embpre, 0);   // embpre ready before first lstm

    // ---- Decode loop ----
    const int chunk_t0[4] = {0, 6, 12, 18};
    const int chunk_nt[4] = {6, 6, 6, 1};
    int ci = 0;
    for (int t = 0; t < NT; t++) {
        // hproj = h @ [w_dec|w_beta|w_hh]^T, split-K=2  (128 x 3072)
        {
            dim3 grid(NHP / TBN, 1, 2);            // (48,1,2)
            gemm_bf16x3<<<grid, 256>>>(p_hh, p_hl, ND, p_wagh, p_wagl, ND,
                                       nullptr, p_hproj, 256, NHP, 0,
                                       (long)NB * NHP, nullptr, 0, 0);
        }
        // fused escore + softmax + context (emits awe split)
        k_att<<<NB, 512>>>(lengths, features, w_full, out, ALPHA_OFF, t);
        // awe-gates partials: awe @ w_awe^T, split-K=2  (128 x 2048)
        {
            dim3 grid(NG / TBN, 1, 2);             // (32,1,2)
            gemm_bf16x3<<<grid, 256>>>(p_awehi, p_awelo, ND, p_waweh, p_wawel, ND,
                                       nullptr, p_awep, 256, NG, 0,
                                       (long)NB * NG, nullptr, 0, 0);
        }
        k_lstm<<<NB, ND>>>(lengths, t);

        // chunk boundary -> batched FC for steps [t0, t0+nt) on side stream.
        // permute mode: grid.x = t-tiles (M), grid.y = N-tiles (weight reuse).
        if (ci < 4 && t == chunk_t0[ci] + chunk_nt[ci] - 1) {
            cudaEventRecord(ev_chunk[ci], 0);
            cudaStreamWaitEvent(side, ev_chunk[ci], 0);
            int t0 = chunk_t0[ci], nt = chunk_nt[ci];
            dim3 grid(nt, NV / TBN, 1);            // (nt, 500)
            gemm_bf16x3<<<grid, 256, 0, side>>>(
                p_hnallh + (long)t0 * NB * ND, p_hnalll + (long)t0 * NB * ND, ND,
                p_wfch, p_wfcl, ND,
                b_fc, out, ND, NV, 0, 0,
                lengths, 1, t0);
            ci++;
        }
    }
    cudaEventRecord(evf, side);
    cudaStreamWaitEvent(0, evf, 0);
}